// round 10
// baseline (speedup 1.0000x reference)
#include <cuda_runtime.h>
#include <cuda_fp16.h>
#include <cstdint>
#include <math.h>

// Problem dims
#define N_B   32
#define T_B   243
#define V_B   17
#define NT_B  (N_B * T_B)          // 7776
#define MROWS (NT_B * V_B)         // 132192

// ---------------- scratch (static device memory; no allocations) ----------
__device__ __half g_xc [67682304];   // M*512  concat (xm_out | xa_out)
__device__ __half g_qkv[50761728];   // M*384
__device__ __half g_o  [16920576];   // M*128
__device__ __half g_h  [135364608];  // M*1024
__device__ __half h_xa [16920576];   // M*128  normalized attn input
__device__ __half h_xn [67682304];   // M*512  normalized MLP input
__device__ __half h_in_w [49152];
__device__ __half h_out_w[16384];
__device__ __half h_cm_w1[524288];
__device__ __half h_cm_w2[524288];

// ---------------- helpers -------------------------------------------------
__device__ __forceinline__ float gelu_f(float v) {
    return 0.5f * v * (1.0f + erff(v * 0.7071067811865475f));
}
__device__ __forceinline__ uint32_t smaddr(const void* p) {
    return (uint32_t)__cvta_generic_to_shared(p);
}
__device__ __forceinline__ void ldsm4(uint32_t* r, uint32_t a) {
    asm volatile("ldmatrix.sync.aligned.m8n8.x4.shared.b16 {%0,%1,%2,%3}, [%4];"
        : "=r"(r[0]), "=r"(r[1]), "=r"(r[2]), "=r"(r[3]) : "r"(a));
}
__device__ __forceinline__ void hmma(float* d, const uint32_t* a, const uint32_t* b) {
    asm volatile(
        "mma.sync.aligned.m16n8k16.row.col.f32.f16.f16.f32 "
        "{%0,%1,%2,%3},{%4,%5,%6,%7},{%8,%9},{%0,%1,%2,%3};"
        : "+f"(d[0]), "+f"(d[1]), "+f"(d[2]), "+f"(d[3])
        : "r"(a[0]), "r"(a[1]), "r"(a[2]), "r"(a[3]), "r"(b[0]), "r"(b[1]));
}
__device__ __forceinline__ void cp16(uint32_t dst, const void* src, bool pred) {
    int sz = pred ? 16 : 0;
    asm volatile("cp.async.cg.shared.global [%0], [%1], 16, %2;\n"
        :: "r"(dst), "l"(src), "r"(sz));
}
__device__ __forceinline__ void cp_commit() {
    asm volatile("cp.async.commit_group;\n" ::: "memory");
}
template <int NN>
__device__ __forceinline__ void cp_wait() {
    asm volatile("cp.async.wait_group %0;\n" :: "n"(NN) : "memory");
}

// ---------------- fp16 GEMM: out = act(A * W^T + bias) --------------------
// CTA tile 128(M) x 64(N), 8 warps of 32x32, K-tile 64, 3-stage cp.async.
// Stage: A 128x64h (16KB) + B 64x64h (8KB) = 24KB; 3 stages = 72KB -> 3 CTAs/SM.
// MODE: 0 = bias, 1 = bias+gelu, 2 = bias+residual(fp32 x, stride 512)
#define STAGE_BYTES 24576
#define GEMM_SMEM   (3 * STAGE_BYTES + 128)

template <int MODE, typename OT>
__device__ __forceinline__ void gemm_core(
    const __half* __restrict__ A, int lda,
    const __half* __restrict__ W, int K,
    const float* __restrict__ bias,
    const float* __restrict__ residual,
    OT* __restrict__ out, int ldc, int coff,
    int M)
{
    extern __shared__ char dynsmem[];
    const uint32_t sb = (smaddr(dynsmem) + 127u) & ~127u;

    const int tid  = threadIdx.x;
    const int lane = tid & 31;
    const int warp = tid >> 5;
    const int wm   = (warp & 3) * 32;    // 4 warps along M
    const int wn   = (warp >> 2) * 32;   // 2 warps along N
    const int n0   = blockIdx.x * 64;    // N fastest -> A-tile L2 reuse
    const int m0   = blockIdx.y * 128;

    uint32_t stA[3], stB[3];
#pragma unroll
    for (int s = 0; s < 3; s++) { stA[s] = sb + s * STAGE_BYTES; stB[s] = stA[s] + 16384; }

    float acc[2][4][4] = {};

    // stage: A 128 rows + B 64 rows, 64 halfs (128B) per row, XOR-swizzled.
    // 1536 16B-chunks total -> 6 per thread.
    auto stage_load = [&](int s, int kk) {
#pragma unroll
        for (int i = 0; i < 4; i++) {               // A: chunks 0..1023
            int ch  = tid + i * 256;
            int r   = ch >> 3, c16 = ch & 7;
            uint32_t swo = (uint32_t)(r * 128 + c16 * 16) ^ (uint32_t)((r & 7) << 4);
            cp16(stA[s] + swo, A + (size_t)(m0 + r) * lda + kk + c16 * 8, (m0 + r) < M);
        }
#pragma unroll
        for (int i = 0; i < 2; i++) {               // B: chunks 0..511
            int ch  = tid + i * 256;
            int r   = ch >> 3, c16 = ch & 7;
            uint32_t swo = (uint32_t)(r * 128 + c16 * 16) ^ (uint32_t)((r & 7) << 4);
            cp16(stB[s] + swo, W + (size_t)(n0 + r) * K + kk + c16 * 8, true);
        }
    };

    auto compute = [&](int s) {
#pragma unroll
        for (int ks = 0; ks < 4; ks++) {
            const int c = ks * 16 + 8 * (lane >> 4);
            uint32_t a[2][4], b[2][4];
#pragma unroll
            for (int mt = 0; mt < 2; mt++) {
                int r = wm + mt * 16 + (lane & 15);
                ldsm4(a[mt], stA[s] + ((uint32_t)(r * 128 + c * 2) ^ (uint32_t)((r & 7) << 4)));
            }
#pragma unroll
            for (int np = 0; np < 2; np++) {
                int r = wn + np * 16 + (lane & 15);
                ldsm4(b[np], stB[s] + ((uint32_t)(r * 128 + c * 2) ^ (uint32_t)((r & 7) << 4)));
            }
#pragma unroll
            for (int mt = 0; mt < 2; mt++)
#pragma unroll
                for (int nt = 0; nt < 4; nt++) {
                    uint32_t bb[2] = { b[nt >> 1][nt & 1], b[nt >> 1][(nt & 1) + 2] };
                    hmma(acc[mt][nt], a[mt], bb);
                }
        }
    };

    const int nT = K >> 6;
    int fetch = 0;
#pragma unroll
    for (int s = 0; s < 2; s++) {
        if (fetch < nT) stage_load(fetch, fetch << 6);
        cp_commit();
        fetch++;
    }
    for (int t = 0; t < nT; t++) {
        cp_wait<1>();
        __syncthreads();
        compute(t % 3);
        if (fetch < nT) stage_load(fetch % 3, fetch << 6);
        cp_commit();
        fetch++;
    }

    // epilogue
    const int er = lane >> 2;
    const int ec = (lane & 3) * 2;
#pragma unroll
    for (int mt = 0; mt < 2; mt++) {
#pragma unroll
        for (int hh = 0; hh < 2; hh++) {
            int row = m0 + wm + mt * 16 + er + hh * 8;
            if (row >= M) continue;
#pragma unroll
            for (int nt = 0; nt < 4; nt++) {
                int col  = wn + nt * 8 + ec;
                int gcol = n0 + col;
                float v0 = acc[mt][nt][hh * 2 + 0] + bias[gcol];
                float v1 = acc[mt][nt][hh * 2 + 1] + bias[gcol + 1];
                if (MODE == 1) { v0 = gelu_f(v0); v1 = gelu_f(v1); }
                if (MODE == 2) {
                    const float* rp = residual + (size_t)row * 512 + coff + gcol;
                    v0 += rp[0]; v1 += rp[1];
                }
                if constexpr (sizeof(OT) == 2) {
                    *(__half2*)(out + (size_t)row * ldc + coff + gcol) =
                        __floats2half2_rn(v0, v1);
                } else {
                    *(float2*)(out + (size_t)row * ldc + coff + gcol) =
                        make_float2(v0, v1);
                }
            }
        }
    }
}

// ---------------- GEMM wrappers ------------------------------------------
__global__ __launch_bounds__(256, 3) void k_gemm_qkv(const float* __restrict__ in_b) {
    gemm_core<0, __half>(h_xa, 128, h_in_w, 128, in_b, nullptr,
                         g_qkv, 384, 0, MROWS);
}
__global__ __launch_bounds__(256, 3) void k_gemm_proj(const float* __restrict__ out_b) {
    gemm_core<0, __half>(g_o, 128, h_out_w, 128, out_b, nullptr,
                         g_xc, 512, 384, MROWS);
}
__global__ __launch_bounds__(256, 3) void k_gemm_mlp1(const float* __restrict__ cm_b1) {
    gemm_core<1, __half>(h_xn, 512, h_cm_w1, 512, cm_b1, nullptr,
                         g_h, 1024, 0, MROWS);
}
__global__ __launch_bounds__(256, 3) void k_gemm_mlp2(
    const float* __restrict__ cm_b2, const float* __restrict__ x,
    float* __restrict__ out)
{
    gemm_core<2, float>(g_h, 1024, h_cm_w2, 1024, cm_b2, x,
                        out, 512, 0, MROWS);
}

// ---------------- weight conversion fp32 -> fp16 --------------------------
__global__ __launch_bounds__(256) void k_cvt_w(
    const float* __restrict__ in_w, const float* __restrict__ out_w,
    const float* __restrict__ cm_w1, const float* __restrict__ cm_w2)
{
    int i = blockIdx.x * 256 + threadIdx.x;
    if (i < 49152) h_in_w[i] = __float2half(in_w[i]);
    if (i < 16384) h_out_w[i] = __float2half(out_w[i]);
    if (i < 524288) {
        h_cm_w1[i] = __float2half(cm_w1[i]);
        h_cm_w2[i] = __float2half(cm_w2[i]);
    }
}

// ---------------- token mixer (mix over V=17, channels d<384) -------------
__global__ __launch_bounds__(384) void k_tokenmix(
    const float* __restrict__ x,
    const float* __restrict__ w1, const float* __restrict__ b1,
    const float* __restrict__ w2, const float* __restrict__ b2)
{
    __shared__ float sw1[289], sw2[289], sb1[17], sb2[17];
    int tid = threadIdx.x;
    if (tid < 289) { sw1[tid] = w1[tid]; sw2[tid] = w2[tid]; }
    if (tid < 17)  { sb1[tid] = b1[tid]; sb2[tid] = b2[tid]; }
    __syncthreads();

    size_t base = (size_t)blockIdx.x * V_B * 512;
    int d = tid;  // 0..383
    float xv[17];
#pragma unroll
    for (int v = 0; v < 17; v++) xv[v] = x[base + (size_t)v * 512 + d];
    float h[17];
#pragma unroll
    for (int u = 0; u < 17; u++) {
        float s = sb1[u];
#pragma unroll
        for (int v = 0; v < 17; v++) s += sw1[u * 17 + v] * xv[v];
        h[u] = gelu_f(s);
    }
#pragma unroll
    for (int u = 0; u < 17; u++) {
        float s = sb2[u];
#pragma unroll
        for (int v = 0; v < 17; v++) s += sw2[u * 17 + v] * h[v];
        g_xc[base + (size_t)u * 512 + d] = __float2half(s);
    }
}

// ---------------- RMSNorm prep: write normalized fp16 A -------------------
__global__ __launch_bounds__(256) void k_prep_a(
    const float* __restrict__ x, const float* __restrict__ na_w)
{
    int row = blockIdx.x * 8 + (threadIdx.x >> 5);
    if (row >= MROWS) return;
    int lane = threadIdx.x & 31;
    const float* p = x + (size_t)row * 512 + 384;
    float4 v = *(const float4*)(p + lane * 4);
    float ss = v.x * v.x + v.y * v.y + v.z * v.z + v.w * v.w;
#pragma unroll
    for (int s = 16; s; s >>= 1) ss += __shfl_xor_sync(0xffffffffu, ss, s);
    float r = rsqrtf(ss * (1.0f / 128.0f) + 1e-6f);
    float4 w = *(const float4*)(na_w + lane * 4);
    __half2* o = (__half2*)(h_xa + (size_t)row * 128 + lane * 4);
    o[0] = __floats2half2_rn(v.x * r * w.x, v.y * r * w.y);
    o[1] = __floats2half2_rn(v.z * r * w.z, v.w * r * w.w);
}

__global__ __launch_bounds__(256) void k_prep_f(const float* __restrict__ nf_w) {
    int row = blockIdx.x * 8 + (threadIdx.x >> 5);
    if (row >= MROWS) return;
    int lane = threadIdx.x & 31;
    const __half* p = g_xc + (size_t)row * 512;
    float vals[16];
    float ss = 0.f;
#pragma unroll
    for (int c = 0; c < 2; c++) {
        uint4 u = *(const uint4*)(p + lane * 8 + c * 256);
        __half2* h = (__half2*)&u;
#pragma unroll
        for (int j = 0; j < 4; j++) {
            float2 f = __half22float2(h[j]);
            vals[c * 8 + j * 2] = f.x; vals[c * 8 + j * 2 + 1] = f.y;
            ss += f.x * f.x + f.y * f.y;
        }
    }
#pragma unroll
    for (int s = 16; s; s >>= 1) ss += __shfl_xor_sync(0xffffffffu, ss, s);
    float r = rsqrtf(ss * (1.0f / 512.0f) + 1e-6f);
    __half* o = h_xn + (size_t)row * 512;
#pragma unroll
    for (int c = 0; c < 2; c++) {
        int base = lane * 8 + c * 256;
        __half2 hh[4];
#pragma unroll
        for (int j = 0; j < 4; j++) {
            float w0 = nf_w[base + j * 2], w1 = nf_w[base + j * 2 + 1];
            hh[j] = __floats2half2_rn(vals[c * 8 + j * 2] * r * w0,
                                      vals[c * 8 + j * 2 + 1] * r * w1);
        }
        *(uint4*)(o + base) = *(uint4*)hh;
    }
}

// ---------------- attention: one WARP per (n*t, head) ---------------------
__global__ void k_attn() {
    __shared__ __align__(16) float s[17 * 64];   // per row: k[32] | v[32]
    int bh = blockIdx.x;
    int b  = bh >> 2;
    int hh = bh & 3;
    int lane = threadIdx.x;

    const __half* src = g_qkv + (size_t)b * (17 * 384) + hh * 32;

    // load K,V slices: 17 rows x 2 mats x 4 16B-chunks = 136 chunks
    for (int c = lane; c < 136; c += 32) {
        int row  = c >> 3;
        int m    = (c & 7) >> 2;           // 0 = K, 1 = V
        int part = c & 3;
        uint4 u = *(const uint4*)(src + (size_t)row * 384 + 128 + m * 128 + part * 8);
        float* dst = &s[row * 64 + m * 32 + part * 8];
        __half2* h = (__half2*)&u;
#pragma unroll
        for (int j = 0; j < 4; j++) {
            float2 f = __half22float2(h[j]);
            dst[j * 2] = f.x; dst[j * 2 + 1] = f.y;
        }
    }
    __syncwarp();

    if (lane < 17) {
        int q = lane;
        // q vector straight to registers
        float qv[32];
        const uint4* qp = (const uint4*)(src + (size_t)q * 384);
#pragma unroll
        for (int i = 0; i < 4; i++) {
            uint4 u = qp[i];
            __half2* h = (__half2*)&u;
#pragma unroll
            for (int j = 0; j < 4; j++) {
                float2 f = __half22float2(h[j]);
                qv[i * 8 + j * 2] = f.x; qv[i * 8 + j * 2 + 1] = f.y;
            }
        }
        float sc[17];
        float mx = -1e30f;
#pragma unroll
        for (int j = 0; j < 17; j++) {
            const float* kp = &s[j * 64];
            float a = 0.f;
#pragma unroll
            for (int i = 0; i < 8; i++) {
                float4 v = *(const float4*)(kp + i * 4);
                a += qv[i * 4] * v.x + qv[i * 4 + 1] * v.y +
                     qv[i * 4 + 2] * v.z + qv[i * 4 + 3] * v.w;
            }
            a *= 0.17677669529663687f;   // 1/sqrt(32)
            sc[j] = a;
            mx = fmaxf(mx, a);
        }
        float sum = 0.f;
#pragma unroll
        for (int j = 0; j < 17; j++) { sc[j] = __expf(sc[j] - mx); sum += sc[j]; }
        float inv = 1.f / sum;
        float ov[32];
#pragma unroll
        for (int i = 0; i < 32; i++) ov[i] = 0.f;
#pragma unroll
        for (int j = 0; j < 17; j++) {
            float p = sc[j] * inv;
            const float* vp = &s[j * 64 + 32];
#pragma unroll
            for (int i = 0; i < 8; i++) {
                float4 v = *(const float4*)(vp + i * 4);
                ov[i * 4]     += p * v.x;
                ov[i * 4 + 1] += p * v.y;
                ov[i * 4 + 2] += p * v.z;
                ov[i * 4 + 3] += p * v.w;
            }
        }
        __half* op = g_o + ((size_t)b * 17 + q) * 128 + hh * 32;
        union { __half2 h2[16]; uint4 u4[4]; } ob;
#pragma unroll
        for (int i = 0; i < 16; i++)
            ob.h2[i] = __floats2half2_rn(ov[2 * i], ov[2 * i + 1]);
        uint4* o4 = (uint4*)op;
#pragma unroll
        for (int i = 0; i < 4; i++) o4[i] = ob.u4[i];
    }
}

// ---------------- launch --------------------------------------------------
extern "C" void kernel_launch(void* const* d_in, const int* in_sizes, int n_in,
                              void* d_out, int out_size)
{
    const float* x     = (const float*)d_in[0];
    const float* tm_w1 = (const float*)d_in[1];
    const float* tm_b1 = (const float*)d_in[2];
    const float* tm_w2 = (const float*)d_in[3];
    const float* tm_b2 = (const float*)d_in[4];
    const float* na_w  = (const float*)d_in[5];
    const float* in_w  = (const float*)d_in[6];
    const float* in_b  = (const float*)d_in[7];
    const float* out_w = (const float*)d_in[8];
    const float* out_b = (const float*)d_in[9];
    const float* nf_w  = (const float*)d_in[10];
    const float* cm_w1 = (const float*)d_in[11];
    const float* cm_b1 = (const float*)d_in[12];
    const float* cm_w2 = (const float*)d_in[13];
    const float* cm_b2 = (const float*)d_in[14];
    float* out = (float*)d_out;

    const int mt = (MROWS + 127) / 128;  // 1033 M-tiles

    static int attr_done = 0;
    if (!attr_done) {
        cudaFuncSetAttribute(k_gemm_qkv,  cudaFuncAttributeMaxDynamicSharedMemorySize, GEMM_SMEM);
        cudaFuncSetAttribute(k_gemm_proj, cudaFuncAttributeMaxDynamicSharedMemorySize, GEMM_SMEM);
        cudaFuncSetAttribute(k_gemm_mlp1, cudaFuncAttributeMaxDynamicSharedMemorySize, GEMM_SMEM);
        cudaFuncSetAttribute(k_gemm_mlp2, cudaFuncAttributeMaxDynamicSharedMemorySize, GEMM_SMEM);
        attr_done = 1;
    }

    k_cvt_w<<<2048, 256>>>(in_w, out_w, cm_w1, cm_w2);
    k_tokenmix<<<NT_B, 384>>>(x, tm_w1, tm_b1, tm_w2, tm_b2);
    k_prep_a<<<(MROWS + 7) / 8, 256>>>(x, na_w);
    k_gemm_qkv<<<dim3(6, mt), 256, GEMM_SMEM>>>(in_b);
    k_attn<<<NT_B * 4, 32>>>();
    k_gemm_proj<<<dim3(2, mt), 256, GEMM_SMEM>>>(out_b);
    k_prep_f<<<(MROWS + 7) / 8, 256>>>(nf_w);
    k_gemm_mlp1<<<dim3(16, mt), 256, GEMM_SMEM>>>(cm_b1);
    k_gemm_mlp2<<<dim3(8, mt), 256, GEMM_SMEM>>>(cm_b2, x, out);
}

// round 11
// speedup vs baseline: 1.0139x; 1.0139x over previous
#include <cuda_runtime.h>
#include <cuda_fp16.h>
#include <cstdint>
#include <math.h>

// Problem dims
#define N_B   32
#define T_B   243
#define V_B   17
#define NT_B  (N_B * T_B)          // 7776
#define MROWS (NT_B * V_B)         // 132192

// ---------------- scratch (static device memory; no allocations) ----------
__device__ __half g_xc [67682304];   // M*512  concat (xm_out | xa_out)
__device__ __half g_qkv[50761728];   // M*384
__device__ __half g_o  [16920576];   // M*128
__device__ __half g_h  [135364608];  // M*1024
__device__ __half h_xa [16920576];   // M*128  normalized attn input
__device__ __half h_xn [67682304];   // M*512  normalized MLP input
__device__ __half h_in_w [49152];
__device__ __half h_out_w[16384];
__device__ __half h_cm_w1[524288];
__device__ __half h_cm_w2[524288];

// ---------------- helpers -------------------------------------------------
__device__ __forceinline__ float gelu_f(float v) {
    return 0.5f * v * (1.0f + erff(v * 0.7071067811865475f));
}
__device__ __forceinline__ uint32_t smaddr(const void* p) {
    return (uint32_t)__cvta_generic_to_shared(p);
}
__device__ __forceinline__ void ldsm4(uint32_t* r, uint32_t a) {
    asm volatile("ldmatrix.sync.aligned.m8n8.x4.shared.b16 {%0,%1,%2,%3}, [%4];"
        : "=r"(r[0]), "=r"(r[1]), "=r"(r[2]), "=r"(r[3]) : "r"(a));
}
__device__ __forceinline__ void hmma(float* d, const uint32_t* a, const uint32_t* b) {
    asm volatile(
        "mma.sync.aligned.m16n8k16.row.col.f32.f16.f16.f32 "
        "{%0,%1,%2,%3},{%4,%5,%6,%7},{%8,%9},{%0,%1,%2,%3};"
        : "+f"(d[0]), "+f"(d[1]), "+f"(d[2]), "+f"(d[3])
        : "r"(a[0]), "r"(a[1]), "r"(a[2]), "r"(a[3]), "r"(b[0]), "r"(b[1]));
}
__device__ __forceinline__ void cp16(uint32_t dst, const void* src, bool pred) {
    int sz = pred ? 16 : 0;
    asm volatile("cp.async.cg.shared.global [%0], [%1], 16, %2;\n"
        :: "r"(dst), "l"(src), "r"(sz));
}
__device__ __forceinline__ void cp_commit() {
    asm volatile("cp.async.commit_group;\n" ::: "memory");
}
template <int NN>
__device__ __forceinline__ void cp_wait() {
    asm volatile("cp.async.wait_group %0;\n" :: "n"(NN) : "memory");
}

// ---------------- fp16 GEMM: out = act(A * W^T + bias) --------------------
// CTA tile 128(M) x 128(N), 4 warps of 64x64 (hmma:ldsm ratio 4.0),
// K-tile 64, 3-stage cp.async. Stage: A 128x64h + B 128x64h = 32KB;
// 3 stages = 96KB -> 2 CTAs/SM (192KB smem, 8 warps/SM).
// MODE: 0 = bias, 1 = bias+gelu, 2 = bias+residual(fp32 x, stride 512)
#define STAGE_BYTES 32768
#define GEMM_SMEM   (3 * STAGE_BYTES + 128)

template <int MODE, typename OT>
__device__ __forceinline__ void gemm_core(
    const __half* __restrict__ A, int lda,
    const __half* __restrict__ W, int K,
    const float* __restrict__ bias,
    const float* __restrict__ residual,
    OT* __restrict__ out, int ldc, int coff,
    int M)
{
    extern __shared__ char dynsmem[];
    const uint32_t sb = (smaddr(dynsmem) + 127u) & ~127u;

    const int tid  = threadIdx.x;
    const int lane = tid & 31;
    const int warp = tid >> 5;
    const int wm   = (warp & 1) * 64;    // 2 warps along M
    const int wn   = (warp >> 1) * 64;   // 2 warps along N
    const int n0   = blockIdx.x * 128;   // N fastest -> A-tile L2 reuse
    const int m0   = blockIdx.y * 128;

    uint32_t stA[3], stB[3];
#pragma unroll
    for (int s = 0; s < 3; s++) { stA[s] = sb + s * STAGE_BYTES; stB[s] = stA[s] + 16384; }

    float acc[4][8][4] = {};   // 128 accumulator floats / thread

    // stage: A 128 rows + B 128 rows, 64 halfs (128B) per row, XOR-swizzled.
    // 2048 16B-chunks / 128 threads = 16 per thread.
    auto stage_load = [&](int s, int kk) {
#pragma unroll
        for (int i = 0; i < 8; i++) {               // A: chunks 0..1023
            int ch  = tid + i * 128;
            int r   = ch >> 3, c16 = ch & 7;
            uint32_t swo = (uint32_t)(r * 128 + c16 * 16) ^ (uint32_t)((r & 7) << 4);
            cp16(stA[s] + swo, A + (size_t)(m0 + r) * lda + kk + c16 * 8, (m0 + r) < M);
        }
#pragma unroll
        for (int i = 0; i < 8; i++) {               // B: chunks 0..1023
            int ch  = tid + i * 128;
            int r   = ch >> 3, c16 = ch & 7;
            uint32_t swo = (uint32_t)(r * 128 + c16 * 16) ^ (uint32_t)((r & 7) << 4);
            cp16(stB[s] + swo, W + (size_t)(n0 + r) * K + kk + c16 * 8, true);
        }
    };

    auto compute = [&](int s) {
#pragma unroll
        for (int ks = 0; ks < 4; ks++) {
            const int c = ks * 16 + 8 * (lane >> 4);
            uint32_t a[4][4], b[4][4];
#pragma unroll
            for (int mt = 0; mt < 4; mt++) {
                int r = wm + mt * 16 + (lane & 15);
                ldsm4(a[mt], stA[s] + ((uint32_t)(r * 128 + c * 2) ^ (uint32_t)((r & 7) << 4)));
            }
#pragma unroll
            for (int np = 0; np < 4; np++) {
                int r = wn + np * 16 + (lane & 15);
                ldsm4(b[np], stB[s] + ((uint32_t)(r * 128 + c * 2) ^ (uint32_t)((r & 7) << 4)));
            }
#pragma unroll
            for (int mt = 0; mt < 4; mt++)
#pragma unroll
                for (int nt = 0; nt < 8; nt++) {
                    uint32_t bb[2] = { b[nt >> 1][nt & 1], b[nt >> 1][(nt & 1) + 2] };
                    hmma(acc[mt][nt], a[mt], bb);
                }
        }
    };

    const int nT = K >> 6;
    int fetch = 0;
#pragma unroll
    for (int s = 0; s < 2; s++) {
        if (fetch < nT) stage_load(fetch, fetch << 6);
        cp_commit();
        fetch++;
    }
    for (int t = 0; t < nT; t++) {
        cp_wait<1>();
        __syncthreads();
        compute(t % 3);
        if (fetch < nT) stage_load(fetch % 3, fetch << 6);
        cp_commit();
        fetch++;
    }

    // epilogue
    const int er = lane >> 2;
    const int ec = (lane & 3) * 2;
#pragma unroll
    for (int mt = 0; mt < 4; mt++) {
#pragma unroll
        for (int hh = 0; hh < 2; hh++) {
            int row = m0 + wm + mt * 16 + er + hh * 8;
            if (row >= M) continue;
#pragma unroll
            for (int nt = 0; nt < 8; nt++) {
                int col  = wn + nt * 8 + ec;
                int gcol = n0 + col;
                float v0 = acc[mt][nt][hh * 2 + 0] + bias[gcol];
                float v1 = acc[mt][nt][hh * 2 + 1] + bias[gcol + 1];
                if (MODE == 1) { v0 = gelu_f(v0); v1 = gelu_f(v1); }
                if (MODE == 2) {
                    const float* rp = residual + (size_t)row * 512 + coff + gcol;
                    v0 += rp[0]; v1 += rp[1];
                }
                if constexpr (sizeof(OT) == 2) {
                    *(__half2*)(out + (size_t)row * ldc + coff + gcol) =
                        __floats2half2_rn(v0, v1);
                } else {
                    *(float2*)(out + (size_t)row * ldc + coff + gcol) =
                        make_float2(v0, v1);
                }
            }
        }
    }
}

// ---------------- GEMM wrappers ------------------------------------------
__global__ __launch_bounds__(128, 2) void k_gemm_qkv(const float* __restrict__ in_b) {
    gemm_core<0, __half>(h_xa, 128, h_in_w, 128, in_b, nullptr,
                         g_qkv, 384, 0, MROWS);
}
__global__ __launch_bounds__(128, 2) void k_gemm_proj(const float* __restrict__ out_b) {
    gemm_core<0, __half>(g_o, 128, h_out_w, 128, out_b, nullptr,
                         g_xc, 512, 384, MROWS);
}
__global__ __launch_bounds__(128, 2) void k_gemm_mlp1(const float* __restrict__ cm_b1) {
    gemm_core<1, __half>(h_xn, 512, h_cm_w1, 512, cm_b1, nullptr,
                         g_h, 1024, 0, MROWS);
}
__global__ __launch_bounds__(128, 2) void k_gemm_mlp2(
    const float* __restrict__ cm_b2, const float* __restrict__ x,
    float* __restrict__ out)
{
    gemm_core<2, float>(g_h, 1024, h_cm_w2, 1024, cm_b2, x,
                        out, 512, 0, MROWS);
}

// ---------------- weight conversion fp32 -> fp16 --------------------------
__global__ __launch_bounds__(256) void k_cvt_w(
    const float* __restrict__ in_w, const float* __restrict__ out_w,
    const float* __restrict__ cm_w1, const float* __restrict__ cm_w2)
{
    int i = blockIdx.x * 256 + threadIdx.x;
    if (i < 49152) h_in_w[i] = __float2half(in_w[i]);
    if (i < 16384) h_out_w[i] = __float2half(out_w[i]);
    if (i < 524288) {
        h_cm_w1[i] = __float2half(cm_w1[i]);
        h_cm_w2[i] = __float2half(cm_w2[i]);
    }
}

// ---------------- token mixer (mix over V=17, channels d<384) -------------
__global__ __launch_bounds__(384) void k_tokenmix(
    const float* __restrict__ x,
    const float* __restrict__ w1, const float* __restrict__ b1,
    const float* __restrict__ w2, const float* __restrict__ b2)
{
    __shared__ float sw1[289], sw2[289], sb1[17], sb2[17];
    int tid = threadIdx.x;
    if (tid < 289) { sw1[tid] = w1[tid]; sw2[tid] = w2[tid]; }
    if (tid < 17)  { sb1[tid] = b1[tid]; sb2[tid] = b2[tid]; }
    __syncthreads();

    size_t base = (size_t)blockIdx.x * V_B * 512;
    int d = tid;  // 0..383
    float xv[17];
#pragma unroll
    for (int v = 0; v < 17; v++) xv[v] = x[base + (size_t)v * 512 + d];
    float h[17];
#pragma unroll
    for (int u = 0; u < 17; u++) {
        float s = sb1[u];
#pragma unroll
        for (int v = 0; v < 17; v++) s += sw1[u * 17 + v] * xv[v];
        h[u] = gelu_f(s);
    }
#pragma unroll
    for (int u = 0; u < 17; u++) {
        float s = sb2[u];
#pragma unroll
        for (int v = 0; v < 17; v++) s += sw2[u * 17 + v] * h[v];
        g_xc[base + (size_t)u * 512 + d] = __float2half(s);
    }
}

// ---------------- RMSNorm prep: write normalized fp16 A -------------------
__global__ __launch_bounds__(256) void k_prep_a(
    const float* __restrict__ x, const float* __restrict__ na_w)
{
    int row = blockIdx.x * 8 + (threadIdx.x >> 5);
    if (row >= MROWS) return;
    int lane = threadIdx.x & 31;
    const float* p = x + (size_t)row * 512 + 384;
    float4 v = *(const float4*)(p + lane * 4);
    float ss = v.x * v.x + v.y * v.y + v.z * v.z + v.w * v.w;
#pragma unroll
    for (int s = 16; s; s >>= 1) ss += __shfl_xor_sync(0xffffffffu, ss, s);
    float r = rsqrtf(ss * (1.0f / 128.0f) + 1e-6f);
    float4 w = *(const float4*)(na_w + lane * 4);
    __half2* o = (__half2*)(h_xa + (size_t)row * 128 + lane * 4);
    o[0] = __floats2half2_rn(v.x * r * w.x, v.y * r * w.y);
    o[1] = __floats2half2_rn(v.z * r * w.z, v.w * r * w.w);
}

__global__ __launch_bounds__(256) void k_prep_f(const float* __restrict__ nf_w) {
    int row = blockIdx.x * 8 + (threadIdx.x >> 5);
    if (row >= MROWS) return;
    int lane = threadIdx.x & 31;
    const __half* p = g_xc + (size_t)row * 512;
    float vals[16];
    float ss = 0.f;
#pragma unroll
    for (int c = 0; c < 2; c++) {
        uint4 u = *(const uint4*)(p + lane * 8 + c * 256);
        __half2* h = (__half2*)&u;
#pragma unroll
        for (int j = 0; j < 4; j++) {
            float2 f = __half22float2(h[j]);
            vals[c * 8 + j * 2] = f.x; vals[c * 8 + j * 2 + 1] = f.y;
            ss += f.x * f.x + f.y * f.y;
        }
    }
#pragma unroll
    for (int s = 16; s; s >>= 1) ss += __shfl_xor_sync(0xffffffffu, ss, s);
    float r = rsqrtf(ss * (1.0f / 512.0f) + 1e-6f);
    __half* o = h_xn + (size_t)row * 512;
#pragma unroll
    for (int c = 0; c < 2; c++) {
        int base = lane * 8 + c * 256;
        __half2 hh[4];
#pragma unroll
        for (int j = 0; j < 4; j++) {
            float w0 = nf_w[base + j * 2], w1 = nf_w[base + j * 2 + 1];
            hh[j] = __floats2half2_rn(vals[c * 8 + j * 2] * r * w0,
                                      vals[c * 8 + j * 2 + 1] * r * w1);
        }
        *(uint4*)(o + base) = *(uint4*)hh;
    }
}

// ---------------- attention: one warp per (n*t, head), 8 warps/CTA --------
__global__ __launch_bounds__(256) void k_attn() {
    __shared__ __align__(16) float s[8][17 * 64];   // per row: k[32] | v[32]
    int wrp  = threadIdx.x >> 5;
    int lane = threadIdx.x & 31;
    int bh = blockIdx.x * 8 + wrp;
    int b  = bh >> 2;
    int hh = bh & 3;

    const __half* src = g_qkv + (size_t)b * (17 * 384) + hh * 32;
    float* sm = s[wrp];

    // load K,V slices: 17 rows x 2 mats x 4 16B-chunks = 136 chunks
    for (int c = lane; c < 136; c += 32) {
        int row  = c >> 3;
        int m    = (c & 7) >> 2;           // 0 = K, 1 = V
        int part = c & 3;
        uint4 u = *(const uint4*)(src + (size_t)row * 384 + 128 + m * 128 + part * 8);
        float* dst = &sm[row * 64 + m * 32 + part * 8];
        __half2* h = (__half2*)&u;
#pragma unroll
        for (int j = 0; j < 4; j++) {
            float2 f = __half22float2(h[j]);
            dst[j * 2] = f.x; dst[j * 2 + 1] = f.y;
        }
    }
    __syncwarp();

    if (lane < 17) {
        int q = lane;
        float qv[32];
        const uint4* qp = (const uint4*)(src + (size_t)q * 384);
#pragma unroll
        for (int i = 0; i < 4; i++) {
            uint4 u = qp[i];
            __half2* h = (__half2*)&u;
#pragma unroll
            for (int j = 0; j < 4; j++) {
                float2 f = __half22float2(h[j]);
                qv[i * 8 + j * 2] = f.x; qv[i * 8 + j * 2 + 1] = f.y;
            }
        }
        float sc[17];
        float mx = -1e30f;
#pragma unroll
        for (int j = 0; j < 17; j++) {
            const float* kp = &sm[j * 64];
            float a = 0.f;
#pragma unroll
            for (int i = 0; i < 8; i++) {
                float4 v = *(const float4*)(kp + i * 4);
                a += qv[i * 4] * v.x + qv[i * 4 + 1] * v.y +
                     qv[i * 4 + 2] * v.z + qv[i * 4 + 3] * v.w;
            }
            a *= 0.17677669529663687f;   // 1/sqrt(32)
            sc[j] = a;
            mx = fmaxf(mx, a);
        }
        float sum = 0.f;
#pragma unroll
        for (int j = 0; j < 17; j++) { sc[j] = __expf(sc[j] - mx); sum += sc[j]; }
        float inv = 1.f / sum;
        float ov[32];
#pragma unroll
        for (int i = 0; i < 32; i++) ov[i] = 0.f;
#pragma unroll
        for (int j = 0; j < 17; j++) {
            float p = sc[j] * inv;
            const float* vp = &sm[j * 64 + 32];
#pragma unroll
            for (int i = 0; i < 8; i++) {
                float4 v = *(const float4*)(vp + i * 4);
                ov[i * 4]     += p * v.x;
                ov[i * 4 + 1] += p * v.y;
                ov[i * 4 + 2] += p * v.z;
                ov[i * 4 + 3] += p * v.w;
            }
        }
        __half* op = g_o + ((size_t)b * 17 + q) * 128 + hh * 32;
        union { __half2 h2[16]; uint4 u4[4]; } ob;
#pragma unroll
        for (int i = 0; i < 16; i++)
            ob.h2[i] = __floats2half2_rn(ov[2 * i], ov[2 * i + 1]);
        uint4* o4 = (uint4*)op;
#pragma unroll
        for (int i = 0; i < 4; i++) o4[i] = ob.u4[i];
    }
}

// ---------------- launch --------------------------------------------------
extern "C" void kernel_launch(void* const* d_in, const int* in_sizes, int n_in,
                              void* d_out, int out_size)
{
    const float* x     = (const float*)d_in[0];
    const float* tm_w1 = (const float*)d_in[1];
    const float* tm_b1 = (const float*)d_in[2];
    const float* tm_w2 = (const float*)d_in[3];
    const float* tm_b2 = (const float*)d_in[4];
    const float* na_w  = (const float*)d_in[5];
    const float* in_w  = (const float*)d_in[6];
    const float* in_b  = (const float*)d_in[7];
    const float* out_w = (const float*)d_in[8];
    const float* out_b = (const float*)d_in[9];
    const float* nf_w  = (const float*)d_in[10];
    const float* cm_w1 = (const float*)d_in[11];
    const float* cm_b1 = (const float*)d_in[12];
    const float* cm_w2 = (const float*)d_in[13];
    const float* cm_b2 = (const float*)d_in[14];
    float* out = (float*)d_out;

    const int mt = (MROWS + 127) / 128;  // 1033 M-tiles

    static int attr_done = 0;
    if (!attr_done) {
        cudaFuncSetAttribute(k_gemm_qkv,  cudaFuncAttributeMaxDynamicSharedMemorySize, GEMM_SMEM);
        cudaFuncSetAttribute(k_gemm_proj, cudaFuncAttributeMaxDynamicSharedMemorySize, GEMM_SMEM);
        cudaFuncSetAttribute(k_gemm_mlp1, cudaFuncAttributeMaxDynamicSharedMemorySize, GEMM_SMEM);
        cudaFuncSetAttribute(k_gemm_mlp2, cudaFuncAttributeMaxDynamicSharedMemorySize, GEMM_SMEM);
        attr_done = 1;
    }

    k_cvt_w<<<2048, 256>>>(in_w, out_w, cm_w1, cm_w2);
    k_tokenmix<<<NT_B, 384>>>(x, tm_w1, tm_b1, tm_w2, tm_b2);
    k_prep_a<<<(MROWS + 7) / 8, 256>>>(x, na_w);
    k_gemm_qkv<<<dim3(3, mt), 128, GEMM_SMEM>>>(in_b);
    k_attn<<<NT_B / 2, 256>>>();
    k_gemm_proj<<<dim3(1, mt), 128, GEMM_SMEM>>>(out_b);
    k_prep_f<<<(MROWS + 7) / 8, 256>>>(nf_w);
    k_gemm_mlp1<<<dim3(8, mt), 128, GEMM_SMEM>>>(cm_b1);
    k_gemm_mlp2<<<dim3(4, mt), 128, GEMM_SMEM>>>(cm_b2, x, out);
}

// round 12
// speedup vs baseline: 1.0522x; 1.0377x over previous
#include <cuda_runtime.h>
#include <cuda_fp16.h>
#include <cstdint>
#include <math.h>

// Problem dims
#define N_B   32
#define T_B   243
#define V_B   17
#define NT_B  (N_B * T_B)          // 7776
#define MROWS (NT_B * V_B)         // 132192

// ---------------- scratch (static device memory; no allocations) ----------
__device__ __half g_xc [67682304];   // M*512  concat (xm_out | xa_out)
__device__ __half g_qkv[50761728];   // M*384
__device__ __half g_o  [16920576];   // M*128
__device__ __half g_h  [135364608];  // M*1024
__device__ __half h_xa [16920576];   // M*128  normalized attn input
__device__ __half h_xn [67682304];   // M*512  normalized MLP input
__device__ __half h_in_w [49152];
__device__ __half h_out_w[16384];
__device__ __half h_cm_w1[524288];
__device__ __half h_cm_w2[524288];

// ---------------- helpers -------------------------------------------------
__device__ __forceinline__ float gelu_f(float v) {
    return 0.5f * v * (1.0f + erff(v * 0.7071067811865475f));
}
__device__ __forceinline__ uint32_t smaddr(const void* p) {
    return (uint32_t)__cvta_generic_to_shared(p);
}
__device__ __forceinline__ void ldsm4(uint32_t* r, uint32_t a) {
    asm volatile("ldmatrix.sync.aligned.m8n8.x4.shared.b16 {%0,%1,%2,%3}, [%4];"
        : "=r"(r[0]), "=r"(r[1]), "=r"(r[2]), "=r"(r[3]) : "r"(a));
}
__device__ __forceinline__ void ldsm2(uint32_t* r, uint32_t a) {
    asm volatile("ldmatrix.sync.aligned.m8n8.x2.shared.b16 {%0,%1}, [%2];"
        : "=r"(r[0]), "=r"(r[1]) : "r"(a));
}
__device__ __forceinline__ void hmma(float* d, const uint32_t* a, const uint32_t* b) {
    asm volatile(
        "mma.sync.aligned.m16n8k16.row.col.f32.f16.f16.f32 "
        "{%0,%1,%2,%3},{%4,%5,%6,%7},{%8,%9},{%0,%1,%2,%3};"
        : "+f"(d[0]), "+f"(d[1]), "+f"(d[2]), "+f"(d[3])
        : "r"(a[0]), "r"(a[1]), "r"(a[2]), "r"(a[3]), "r"(b[0]), "r"(b[1]));
}
__device__ __forceinline__ void cp16(uint32_t dst, const void* src, bool pred) {
    int sz = pred ? 16 : 0;
    asm volatile("cp.async.cg.shared.global [%0], [%1], 16, %2;\n"
        :: "r"(dst), "l"(src), "r"(sz));
}
__device__ __forceinline__ void cp_commit() {
    asm volatile("cp.async.commit_group;\n" ::: "memory");
}
template <int NN>
__device__ __forceinline__ void cp_wait() {
    asm volatile("cp.async.wait_group %0;\n" :: "n"(NN) : "memory");
}

// swizzled offset inside a 128x32 fp16 stage tile (conflict-free for
// cp.async 16B stores and ldmatrix 8x16B reads)
__device__ __forceinline__ int sw_off(int row, int col) {
    return row * 32 + ((((col >> 3) ^ (row >> 1)) & 3) << 3) + (col & 7);
}

// ---------------- fp16 GEMM: out = act(A * W^T + bias) --------------------
// EXACT R5 core (best measured): A: M x K fp16 (lda), W: N x K fp16.
// 128x128x32 tiles, 3-stage cp.async, 8 warps of 64x32.
// MODE: 0 = bias, 1 = bias+gelu, 2 = bias+residual(fp32 x, stride 512)
#define STAGES 3

template <int MODE, typename OT>
__device__ __forceinline__ void gemm_core(
    const __half* __restrict__ A, int lda,
    const __half* __restrict__ W, int K,
    const float* __restrict__ bias,
    const float* __restrict__ residual,
    OT* __restrict__ out, int ldc, int coff,
    int M)
{
    __shared__ __half As[STAGES][128 * 32];
    __shared__ __half Bs[STAGES][128 * 32];

    const int tid  = threadIdx.x;
    const int lane = tid & 31;
    const int warp = tid >> 5;
    const int wm   = (warp & 1) * 64;
    const int wn   = (warp >> 1) * 32;
    const int n0   = blockIdx.x * 128;   // N fastest -> A-tile L2 reuse
    const int m0   = blockIdx.y * 128;

    // staging map: 2 chunks each for A and B per thread per stage
    const int r0 = tid >> 2;             // chunk rows (c = tid, tid+256)
    const int g0 = tid & 3;
    const int r1 = (tid + 256) >> 2;
    const int g1 = g0;                   // (tid+256)&3 == tid&3

    float acc[4][4][4] = {};

    auto issue = [&](int buf, int kk) {
        uint32_t da = smaddr(&As[buf][0]);
        uint32_t db = smaddr(&Bs[buf][0]);
        const __half* ap = A + (size_t)(m0 + r0) * lda + kk + g0 * 8;
        cp16(da + sw_off(r0, g0 * 8) * 2, ap, (m0 + r0) < M);
        ap = A + (size_t)(m0 + r1) * lda + kk + g1 * 8;
        cp16(da + sw_off(r1, g1 * 8) * 2, ap, (m0 + r1) < M);
        const __half* bp = W + (size_t)(n0 + r0) * K + kk + g0 * 8;
        cp16(db + sw_off(r0, g0 * 8) * 2, bp, true);
        bp = W + (size_t)(n0 + r1) * K + kk + g1 * 8;
        cp16(db + sw_off(r1, g1 * 8) * 2, bp, true);
    };

    auto compute = [&](int buf) {
        uint32_t baseA = smaddr(&As[buf][0]);
        uint32_t baseB = smaddr(&Bs[buf][0]);
#pragma unroll
        for (int ks = 0; ks < 2; ks++) {
            const int k0 = ks * 16;
            uint32_t a[4][4], b[4][2];
#pragma unroll
            for (int mt = 0; mt < 4; mt++) {
                int r = wm + mt * 16 + (lane & 15);
                int c = k0 + 8 * (lane >> 4);
                ldsm4(a[mt], baseA + sw_off(r, c) * 2);
            }
#pragma unroll
            for (int nt = 0; nt < 4; nt++) {
                int r = wn + nt * 8 + (lane & 7);
                int c = k0 + 8 * ((lane >> 3) & 1);
                ldsm2(b[nt], baseB + sw_off(r, c) * 2);
            }
#pragma unroll
            for (int mt = 0; mt < 4; mt++)
#pragma unroll
                for (int nt = 0; nt < 4; nt++)
                    hmma(acc[mt][nt], a[mt], b[nt]);
        }
    };

    const int nk = K >> 5;
    int fetch = 0;
#pragma unroll
    for (int s = 0; s < STAGES - 1; s++) {
        if (fetch < nk) issue(fetch % STAGES, fetch << 5);
        cp_commit();
        fetch++;
    }
    for (int kt = 0; kt < nk; kt++) {
        cp_wait<STAGES - 2>();
        __syncthreads();
        compute(kt % STAGES);
        __syncthreads();
        if (fetch < nk) issue(fetch % STAGES, fetch << 5);
        cp_commit();
        fetch++;
    }

    // epilogue
    const int er = lane >> 2;
    const int ec = (lane & 3) * 2;
#pragma unroll
    for (int mt = 0; mt < 4; mt++) {
#pragma unroll
        for (int hh = 0; hh < 2; hh++) {
            int row = m0 + wm + mt * 16 + er + hh * 8;
            if (row >= M) continue;
#pragma unroll
            for (int nt = 0; nt < 4; nt++) {
                int col  = wn + nt * 8 + ec;
                int gcol = n0 + col;
                float v0 = acc[mt][nt][hh * 2 + 0] + bias[gcol];
                float v1 = acc[mt][nt][hh * 2 + 1] + bias[gcol + 1];
                if (MODE == 1) { v0 = gelu_f(v0); v1 = gelu_f(v1); }
                if (MODE == 2) {
                    const float* rp = residual + (size_t)row * 512 + coff + gcol;
                    v0 += rp[0]; v1 += rp[1];
                }
                if constexpr (sizeof(OT) == 2) {
                    *(__half2*)(out + (size_t)row * ldc + coff + gcol) =
                        __floats2half2_rn(v0, v1);
                } else {
                    *(float2*)(out + (size_t)row * ldc + coff + gcol) =
                        make_float2(v0, v1);
                }
            }
        }
    }
}

// ---------------- GEMM wrappers ------------------------------------------
__global__ __launch_bounds__(256, 2) void k_gemm_qkv(const float* __restrict__ in_b) {
    gemm_core<0, __half>(h_xa, 128, h_in_w, 128, in_b, nullptr,
                         g_qkv, 384, 0, MROWS);
}
__global__ __launch_bounds__(256, 2) void k_gemm_proj(const float* __restrict__ out_b) {
    gemm_core<0, __half>(g_o, 128, h_out_w, 128, out_b, nullptr,
                         g_xc, 512, 384, MROWS);
}
__global__ __launch_bounds__(256, 2) void k_gemm_mlp1(const float* __restrict__ cm_b1) {
    gemm_core<1, __half>(h_xn, 512, h_cm_w1, 512, cm_b1, nullptr,
                         g_h, 1024, 0, MROWS);
}
__global__ __launch_bounds__(256, 2) void k_gemm_mlp2(
    const float* __restrict__ cm_b2, const float* __restrict__ x,
    float* __restrict__ out)
{
    gemm_core<2, float>(g_h, 1024, h_cm_w2, 1024, cm_b2, x,
                        out, 512, 0, MROWS);
}

// ---------------- fused: token mixer + prep_a + weight convert ------------
// Blocks [0, NT_B): 512 threads — t<384 do the V-mixer for channel t,
//   t>=384 (4 warps) do RMSNorm-A prep for the block's 17 rows.
// Blocks [NT_B, NT_B+1024): fp32->fp16 weight conversion.
__global__ __launch_bounds__(512) void k_front(
    const float* __restrict__ x,
    const float* __restrict__ w1, const float* __restrict__ b1,
    const float* __restrict__ w2, const float* __restrict__ b2,
    const float* __restrict__ na_w,
    const float* __restrict__ in_w, const float* __restrict__ out_w,
    const float* __restrict__ cm_w1, const float* __restrict__ cm_w2)
{
    int tid = threadIdx.x;
    if (blockIdx.x >= NT_B) {
        int i = (blockIdx.x - NT_B) * 512 + tid;
        if (i < 49152)  h_in_w[i]  = __float2half(in_w[i]);
        if (i < 16384)  h_out_w[i] = __float2half(out_w[i]);
        if (i < 524288) {
            h_cm_w1[i] = __float2half(cm_w1[i]);
            h_cm_w2[i] = __float2half(cm_w2[i]);
        }
        return;
    }

    __shared__ float sw1[289], sw2[289], sb1[17], sb2[17];
    if (tid < 289) { sw1[tid] = w1[tid]; sw2[tid] = w2[tid]; }
    if (tid < 17)  { sb1[tid] = b1[tid]; sb2[tid] = b2[tid]; }
    __syncthreads();

    size_t base = (size_t)blockIdx.x * V_B * 512;

    if (tid < 384) {
        int d = tid;  // channel 0..383
        float xv[17];
#pragma unroll
        for (int v = 0; v < 17; v++) xv[v] = x[base + (size_t)v * 512 + d];
        float h[17];
#pragma unroll
        for (int u = 0; u < 17; u++) {
            float s = sb1[u];
#pragma unroll
            for (int v = 0; v < 17; v++) s += sw1[u * 17 + v] * xv[v];
            h[u] = gelu_f(s);
        }
#pragma unroll
        for (int u = 0; u < 17; u++) {
            float s = sb2[u];
#pragma unroll
            for (int v = 0; v < 17; v++) s += sw2[u * 17 + v] * h[v];
            g_xc[base + (size_t)u * 512 + d] = __float2half(s);
        }
    } else {
        // prep_a for the 17 rows of this (n,t): 4 warps, rows wrp, wrp+4, ...
        int wrp  = (tid - 384) >> 5;
        int lane = tid & 31;
        size_t row0 = (size_t)blockIdx.x * V_B;
        float4 w = *(const float4*)(na_w + lane * 4);
        for (int r = wrp; r < 17; r += 4) {
            size_t row = row0 + r;
            const float* p = x + row * 512 + 384;
            float4 v = *(const float4*)(p + lane * 4);
            float ss = v.x * v.x + v.y * v.y + v.z * v.z + v.w * v.w;
#pragma unroll
            for (int s = 16; s; s >>= 1) ss += __shfl_xor_sync(0xffffffffu, ss, s);
            float rr = rsqrtf(ss * (1.0f / 128.0f) + 1e-6f);
            __half2* o = (__half2*)(h_xa + row * 128 + lane * 4);
            o[0] = __floats2half2_rn(v.x * rr * w.x, v.y * rr * w.y);
            o[1] = __floats2half2_rn(v.z * rr * w.z, v.w * rr * w.w);
        }
    }
}

// ---------------- RMSNorm prep (full row) ---------------------------------
__global__ __launch_bounds__(256) void k_prep_f(const float* __restrict__ nf_w) {
    int row = blockIdx.x * 8 + (threadIdx.x >> 5);
    if (row >= MROWS) return;
    int lane = threadIdx.x & 31;
    const __half* p = g_xc + (size_t)row * 512;
    float vals[16];
    float ss = 0.f;
#pragma unroll
    for (int c = 0; c < 2; c++) {
        uint4 u = *(const uint4*)(p + lane * 8 + c * 256);
        __half2* h = (__half2*)&u;
#pragma unroll
        for (int j = 0; j < 4; j++) {
            float2 f = __half22float2(h[j]);
            vals[c * 8 + j * 2] = f.x; vals[c * 8 + j * 2 + 1] = f.y;
            ss += f.x * f.x + f.y * f.y;
        }
    }
#pragma unroll
    for (int s = 16; s; s >>= 1) ss += __shfl_xor_sync(0xffffffffu, ss, s);
    float r = rsqrtf(ss * (1.0f / 512.0f) + 1e-6f);
    __half* o = h_xn + (size_t)row * 512;
#pragma unroll
    for (int c = 0; c < 2; c++) {
        int base = lane * 8 + c * 256;
        __half2 hh[4];
#pragma unroll
        for (int j = 0; j < 4; j++) {
            float w0 = nf_w[base + j * 2], w1 = nf_w[base + j * 2 + 1];
            hh[j] = __floats2half2_rn(vals[c * 8 + j * 2] * r * w0,
                                      vals[c * 8 + j * 2 + 1] * r * w1);
        }
        *(uint4*)(o + base) = *(uint4*)hh;
    }
}

// ---------------- attention: one warp per (n*t, head), 8 warps/CTA --------
__global__ __launch_bounds__(256) void k_attn() {
    __shared__ __align__(16) float s[8][17 * 64];   // per row: k[32] | v[32]
    int wrp  = threadIdx.x >> 5;
    int lane = threadIdx.x & 31;
    int bh = blockIdx.x * 8 + wrp;
    int b  = bh >> 2;
    int hh = bh & 3;

    const __half* src = g_qkv + (size_t)b * (17 * 384) + hh * 32;
    float* sm = s[wrp];

    // load K,V slices: 17 rows x 2 mats x 4 16B-chunks = 136 chunks
    for (int c = lane; c < 136; c += 32) {
        int row  = c >> 3;
        int m    = (c & 7) >> 2;           // 0 = K, 1 = V
        int part = c & 3;
        uint4 u = *(const uint4*)(src + (size_t)row * 384 + 128 + m * 128 + part * 8);
        float* dst = &sm[row * 64 + m * 32 + part * 8];
        __half2* h = (__half2*)&u;
#pragma unroll
        for (int j = 0; j < 4; j++) {
            float2 f = __half22float2(h[j]);
            dst[j * 2] = f.x; dst[j * 2 + 1] = f.y;
        }
    }
    __syncwarp();

    if (lane < 17) {
        int q = lane;
        float qv[32];
        const uint4* qp = (const uint4*)(src + (size_t)q * 384);
#pragma unroll
        for (int i = 0; i < 4; i++) {
            uint4 u = qp[i];
            __half2* h = (__half2*)&u;
#pragma unroll
            for (int j = 0; j < 4; j++) {
                float2 f = __half22float2(h[j]);
                qv[i * 8 + j * 2] = f.x; qv[i * 8 + j * 2 + 1] = f.y;
            }
        }
        float sc[17];
        float mx = -1e30f;
#pragma unroll
        for (int j = 0; j < 17; j++) {
            const float* kp = &sm[j * 64];
            float a = 0.f;
#pragma unroll
            for (int i = 0; i < 8; i++) {
                float4 v = *(const float4*)(kp + i * 4);
                a += qv[i * 4] * v.x + qv[i * 4 + 1] * v.y +
                     qv[i * 4 + 2] * v.z + qv[i * 4 + 3] * v.w;
            }
            a *= 0.17677669529663687f;   // 1/sqrt(32)
            sc[j] = a;
            mx = fmaxf(mx, a);
        }
        float sum = 0.f;
#pragma unroll
        for (int j = 0; j < 17; j++) { sc[j] = __expf(sc[j] - mx); sum += sc[j]; }
        float inv = 1.f / sum;
        float ov[32];
#pragma unroll
        for (int i = 0; i < 32; i++) ov[i] = 0.f;
#pragma unroll
        for (int j = 0; j < 17; j++) {
            float p = sc[j] * inv;
            const float* vp = &sm[j * 64 + 32];
#pragma unroll
            for (int i = 0; i < 8; i++) {
                float4 v = *(const float4*)(vp + i * 4);
                ov[i * 4]     += p * v.x;
                ov[i * 4 + 1] += p * v.y;
                ov[i * 4 + 2] += p * v.z;
                ov[i * 4 + 3] += p * v.w;
            }
        }
        __half* op = g_o + ((size_t)b * 17 + q) * 128 + hh * 32;
        union { __half2 h2[16]; uint4 u4[4]; } ob;
#pragma unroll
        for (int i = 0; i < 16; i++)
            ob.h2[i] = __floats2half2_rn(ov[2 * i], ov[2 * i + 1]);
        uint4* o4 = (uint4*)op;
#pragma unroll
        for (int i = 0; i < 4; i++) o4[i] = ob.u4[i];
    }
}

// ---------------- launch --------------------------------------------------
extern "C" void kernel_launch(void* const* d_in, const int* in_sizes, int n_in,
                              void* d_out, int out_size)
{
    const float* x     = (const float*)d_in[0];
    const float* tm_w1 = (const float*)d_in[1];
    const float* tm_b1 = (const float*)d_in[2];
    const float* tm_w2 = (const float*)d_in[3];
    const float* tm_b2 = (const float*)d_in[4];
    const float* na_w  = (const float*)d_in[5];
    const float* in_w  = (const float*)d_in[6];
    const float* in_b  = (const float*)d_in[7];
    const float* out_w = (const float*)d_in[8];
    const float* out_b = (const float*)d_in[9];
    const float* nf_w  = (const float*)d_in[10];
    const float* cm_w1 = (const float*)d_in[11];
    const float* cm_b1 = (const float*)d_in[12];
    const float* cm_w2 = (const float*)d_in[13];
    const float* cm_b2 = (const float*)d_in[14];
    float* out = (float*)d_out;

    const int mt = (MROWS + 127) / 128;  // 1033 M-tiles

    k_front<<<NT_B + 1024, 512>>>(x, tm_w1, tm_b1, tm_w2, tm_b2, na_w,
                                  in_w, out_w, cm_w1, cm_w2);
    k_gemm_qkv<<<dim3(3, mt), 256>>>(in_b);
    k_attn<<<NT_B / 2, 256>>>();
    k_gemm_proj<<<dim3(1, mt), 256>>>(out_b);
    k_prep_f<<<(MROWS + 7) / 8, 256>>>(nf_w);
    k_gemm_mlp1<<<dim3(8, mt), 256>>>(cm_b1);
    k_gemm_mlp2<<<dim3(4, mt), 256>>>(cm_b2, x, out);
}

// round 13
// speedup vs baseline: 1.0652x; 1.0124x over previous
#include <cuda_runtime.h>
#include <cuda_fp16.h>
#include <cstdint>
#include <math.h>

// Problem dims
#define N_B   32
#define T_B   243
#define V_B   17
#define NT_B  (N_B * T_B)          // 7776
#define MROWS (NT_B * V_B)         // 132192

// ---------------- scratch (static device memory; no allocations) ----------
__device__ __half g_xc [67682304];   // M*512  concat (xm_out | xa_out)
__device__ __half g_qkv[50761728];   // M*384
__device__ __half g_o  [16920576];   // M*128
__device__ __half g_h  [135364608];  // M*1024
__device__ __half h_xa [16920576];   // M*128  normalized attn input
__device__ __half h_xn [67682304];   // M*512  normalized MLP input
__device__ __half h_in_w [49152];
__device__ __half h_out_w[16384];
__device__ __half h_cm_w1[524288];
__device__ __half h_cm_w2[524288];

// ---------------- helpers -------------------------------------------------
__device__ __forceinline__ float gelu_f(float v) {
    return 0.5f * v * (1.0f + erff(v * 0.7071067811865475f));
}
__device__ __forceinline__ uint32_t smaddr(const void* p) {
    return (uint32_t)__cvta_generic_to_shared(p);
}
__device__ __forceinline__ void ldsm4(uint32_t* r, uint32_t a) {
    asm volatile("ldmatrix.sync.aligned.m8n8.x4.shared.b16 {%0,%1,%2,%3}, [%4];"
        : "=r"(r[0]), "=r"(r[1]), "=r"(r[2]), "=r"(r[3]) : "r"(a));
}
__device__ __forceinline__ void ldsm2(uint32_t* r, uint32_t a) {
    asm volatile("ldmatrix.sync.aligned.m8n8.x2.shared.b16 {%0,%1}, [%2];"
        : "=r"(r[0]), "=r"(r[1]) : "r"(a));
}
// fp16-ACCUMULATE mma: D(f16x2 x2) = A*B + D
__device__ __forceinline__ void hmma16(uint32_t* d, const uint32_t* a, const uint32_t* b) {
    asm volatile(
        "mma.sync.aligned.m16n8k16.row.col.f16.f16.f16.f16 "
        "{%0,%1},{%2,%3,%4,%5},{%6,%7},{%0,%1};"
        : "+r"(d[0]), "+r"(d[1])
        : "r"(a[0]), "r"(a[1]), "r"(a[2]), "r"(a[3]), "r"(b[0]), "r"(b[1]));
}
__device__ __forceinline__ void cp16(uint32_t dst, const void* src, bool pred) {
    int sz = pred ? 16 : 0;
    asm volatile("cp.async.cg.shared.global [%0], [%1], 16, %2;\n"
        :: "r"(dst), "l"(src), "r"(sz));
}
__device__ __forceinline__ void cp_commit() {
    asm volatile("cp.async.commit_group;\n" ::: "memory");
}
template <int NN>
__device__ __forceinline__ void cp_wait() {
    asm volatile("cp.async.wait_group %0;\n" :: "n"(NN) : "memory");
}

// swizzled offset inside a 128x32 fp16 stage tile (conflict-free for
// cp.async 16B stores and ldmatrix 8x16B reads)
__device__ __forceinline__ int sw_off(int row, int col) {
    return row * 32 + ((((col >> 3) ^ (row >> 1)) & 3) << 3) + (col & 7);
}

// ---------------- fp16 GEMM: out = act(A * W^T + bias) --------------------
// R12 structure, fp16 accumulators. A: M x K fp16 (lda), W: N x K fp16.
// 128x128x32 tiles, 3-stage cp.async, 8 warps of 64x32.
// MODE: 0 = bias, 1 = bias+gelu, 2 = bias+residual(fp32 x, stride 512)
#define STAGES 3

template <int MODE, typename OT>
__device__ __forceinline__ void gemm_core(
    const __half* __restrict__ A, int lda,
    const __half* __restrict__ W, int K,
    const float* __restrict__ bias,
    const float* __restrict__ residual,
    OT* __restrict__ out, int ldc, int coff,
    int M)
{
    __shared__ __half As[STAGES][128 * 32];
    __shared__ __half Bs[STAGES][128 * 32];

    const int tid  = threadIdx.x;
    const int lane = tid & 31;
    const int warp = tid >> 5;
    const int wm   = (warp & 1) * 64;
    const int wn   = (warp >> 1) * 32;
    const int n0   = blockIdx.x * 128;   // N fastest -> A-tile L2 reuse
    const int m0   = blockIdx.y * 128;

    // staging map: 2 chunks each for A and B per thread per stage
    const int r0 = tid >> 2;             // chunk rows (c = tid, tid+256)
    const int g0 = tid & 3;
    const int r1 = (tid + 256) >> 2;
    const int g1 = g0;                   // (tid+256)&3 == tid&3

    uint32_t acc[4][4][2] = {};          // fp16x2 accumulators

    auto issue = [&](int buf, int kk) {
        uint32_t da = smaddr(&As[buf][0]);
        uint32_t db = smaddr(&Bs[buf][0]);
        const __half* ap = A + (size_t)(m0 + r0) * lda + kk + g0 * 8;
        cp16(da + sw_off(r0, g0 * 8) * 2, ap, (m0 + r0) < M);
        ap = A + (size_t)(m0 + r1) * lda + kk + g1 * 8;
        cp16(da + sw_off(r1, g1 * 8) * 2, ap, (m0 + r1) < M);
        const __half* bp = W + (size_t)(n0 + r0) * K + kk + g0 * 8;
        cp16(db + sw_off(r0, g0 * 8) * 2, bp, true);
        bp = W + (size_t)(n0 + r1) * K + kk + g1 * 8;
        cp16(db + sw_off(r1, g1 * 8) * 2, bp, true);
    };

    auto compute = [&](int buf) {
        uint32_t baseA = smaddr(&As[buf][0]);
        uint32_t baseB = smaddr(&Bs[buf][0]);
#pragma unroll
        for (int ks = 0; ks < 2; ks++) {
            const int k0 = ks * 16;
            uint32_t a[4][4], b[4][2];
#pragma unroll
            for (int mt = 0; mt < 4; mt++) {
                int r = wm + mt * 16 + (lane & 15);
                int c = k0 + 8 * (lane >> 4);
                ldsm4(a[mt], baseA + sw_off(r, c) * 2);
            }
#pragma unroll
            for (int nt = 0; nt < 4; nt++) {
                int r = wn + nt * 8 + (lane & 7);
                int c = k0 + 8 * ((lane >> 3) & 1);
                ldsm2(b[nt], baseB + sw_off(r, c) * 2);
            }
#pragma unroll
            for (int mt = 0; mt < 4; mt++)
#pragma unroll
                for (int nt = 0; nt < 4; nt++)
                    hmma16(acc[mt][nt], a[mt], b[nt]);
        }
    };

    const int nk = K >> 5;
    int fetch = 0;
#pragma unroll
    for (int s = 0; s < STAGES - 1; s++) {
        if (fetch < nk) issue(fetch % STAGES, fetch << 5);
        cp_commit();
        fetch++;
    }
    for (int kt = 0; kt < nk; kt++) {
        cp_wait<STAGES - 2>();
        __syncthreads();
        compute(kt % STAGES);
        __syncthreads();
        if (fetch < nk) issue(fetch % STAGES, fetch << 5);
        cp_commit();
        fetch++;
    }

    // epilogue: unpack fp16 accumulators
    const int er = lane >> 2;
    const int ec = (lane & 3) * 2;
#pragma unroll
    for (int mt = 0; mt < 4; mt++) {
#pragma unroll
        for (int hh = 0; hh < 2; hh++) {
            int row = m0 + wm + mt * 16 + er + hh * 8;
            if (row >= M) continue;
#pragma unroll
            for (int nt = 0; nt < 4; nt++) {
                int col  = wn + nt * 8 + ec;
                int gcol = n0 + col;
                float2 f = __half22float2(((__half2*)acc[mt][nt])[hh]);
                float v0 = f.x + bias[gcol];
                float v1 = f.y + bias[gcol + 1];
                if (MODE == 1) { v0 = gelu_f(v0); v1 = gelu_f(v1); }
                if (MODE == 2) {
                    const float* rp = residual + (size_t)row * 512 + coff + gcol;
                    v0 += rp[0]; v1 += rp[1];
                }
                if constexpr (sizeof(OT) == 2) {
                    *(__half2*)(out + (size_t)row * ldc + coff + gcol) =
                        __floats2half2_rn(v0, v1);
                } else {
                    *(float2*)(out + (size_t)row * ldc + coff + gcol) =
                        make_float2(v0, v1);
                }
            }
        }
    }
}

// ---------------- GEMM wrappers ------------------------------------------
__global__ __launch_bounds__(256, 2) void k_gemm_qkv(const float* __restrict__ in_b) {
    gemm_core<0, __half>(h_xa, 128, h_in_w, 128, in_b, nullptr,
                         g_qkv, 384, 0, MROWS);
}
__global__ __launch_bounds__(256, 2) void k_gemm_proj(const float* __restrict__ out_b) {
    gemm_core<0, __half>(g_o, 128, h_out_w, 128, out_b, nullptr,
                         g_xc, 512, 384, MROWS);
}
__global__ __launch_bounds__(256, 2) void k_gemm_mlp1(const float* __restrict__ cm_b1) {
    gemm_core<1, __half>(h_xn, 512, h_cm_w1, 512, cm_b1, nullptr,
                         g_h, 1024, 0, MROWS);
}
__global__ __launch_bounds__(256, 2) void k_gemm_mlp2(
    const float* __restrict__ cm_b2, const float* __restrict__ x,
    float* __restrict__ out)
{
    gemm_core<2, float>(g_h, 1024, h_cm_w2, 1024, cm_b2, x,
                        out, 512, 0, MROWS);
}

// ---------------- fused: token mixer + prep_a + weight convert ------------
// Blocks [0, NT_B): 512 threads — t<384 do the V-mixer for channel t,
//   t>=384 (4 warps) do RMSNorm-A prep for the block's 17 rows.
// Blocks [NT_B, NT_B+1024): fp32->fp16 weight conversion.
__global__ __launch_bounds__(512) void k_front(
    const float* __restrict__ x,
    const float* __restrict__ w1, const float* __restrict__ b1,
    const float* __restrict__ w2, const float* __restrict__ b2,
    const float* __restrict__ na_w,
    const float* __restrict__ in_w, const float* __restrict__ out_w,
    const float* __restrict__ cm_w1, const float* __restrict__ cm_w2)
{
    int tid = threadIdx.x;
    if (blockIdx.x >= NT_B) {
        int i = (blockIdx.x - NT_B) * 512 + tid;
        if (i < 49152)  h_in_w[i]  = __float2half(in_w[i]);
        if (i < 16384)  h_out_w[i] = __float2half(out_w[i]);
        if (i < 524288) {
            h_cm_w1[i] = __float2half(cm_w1[i]);
            h_cm_w2[i] = __float2half(cm_w2[i]);
        }
        return;
    }

    __shared__ float sw1[289], sw2[289], sb1[17], sb2[17];
    if (tid < 289) { sw1[tid] = w1[tid]; sw2[tid] = w2[tid]; }
    if (tid < 17)  { sb1[tid] = b1[tid]; sb2[tid] = b2[tid]; }
    __syncthreads();

    size_t base = (size_t)blockIdx.x * V_B * 512;

    if (tid < 384) {
        int d = tid;  // channel 0..383
        float xv[17];
#pragma unroll
        for (int v = 0; v < 17; v++) xv[v] = x[base + (size_t)v * 512 + d];
        float h[17];
#pragma unroll
        for (int u = 0; u < 17; u++) {
            float s = sb1[u];
#pragma unroll
            for (int v = 0; v < 17; v++) s += sw1[u * 17 + v] * xv[v];
            h[u] = gelu_f(s);
        }
#pragma unroll
        for (int u = 0; u < 17; u++) {
            float s = sb2[u];
#pragma unroll
            for (int v = 0; v < 17; v++) s += sw2[u * 17 + v] * h[v];
            g_xc[base + (size_t)u * 512 + d] = __float2half(s);
        }
    } else {
        // prep_a for the 17 rows of this (n,t): 4 warps, rows wrp, wrp+4, ...
        int wrp  = (tid - 384) >> 5;
        int lane = tid & 31;
        size_t row0 = (size_t)blockIdx.x * V_B;
        float4 w = *(const float4*)(na_w + lane * 4);
        for (int r = wrp; r < 17; r += 4) {
            size_t row = row0 + r;
            const float* p = x + row * 512 + 384;
            float4 v = *(const float4*)(p + lane * 4);
            float ss = v.x * v.x + v.y * v.y + v.z * v.z + v.w * v.w;
#pragma unroll
            for (int s = 16; s; s >>= 1) ss += __shfl_xor_sync(0xffffffffu, ss, s);
            float rr = rsqrtf(ss * (1.0f / 128.0f) + 1e-6f);
            __half2* o = (__half2*)(h_xa + row * 128 + lane * 4);
            o[0] = __floats2half2_rn(v.x * rr * w.x, v.y * rr * w.y);
            o[1] = __floats2half2_rn(v.z * rr * w.z, v.w * rr * w.w);
        }
    }
}

// ---------------- RMSNorm prep (full row) ---------------------------------
__global__ __launch_bounds__(256) void k_prep_f(const float* __restrict__ nf_w) {
    int row = blockIdx.x * 8 + (threadIdx.x >> 5);
    if (row >= MROWS) return;
    int lane = threadIdx.x & 31;
    const __half* p = g_xc + (size_t)row * 512;
    float vals[16];
    float ss = 0.f;
#pragma unroll
    for (int c = 0; c < 2; c++) {
        uint4 u = *(const uint4*)(p + lane * 8 + c * 256);
        __half2* h = (__half2*)&u;
#pragma unroll
        for (int j = 0; j < 4; j++) {
            float2 f = __half22float2(h[j]);
            vals[c * 8 + j * 2] = f.x; vals[c * 8 + j * 2 + 1] = f.y;
            ss += f.x * f.x + f.y * f.y;
        }
    }
#pragma unroll
    for (int s = 16; s; s >>= 1) ss += __shfl_xor_sync(0xffffffffu, ss, s);
    float r = rsqrtf(ss * (1.0f / 512.0f) + 1e-6f);
    __half* o = h_xn + (size_t)row * 512;
#pragma unroll
    for (int c = 0; c < 2; c++) {
        int base = lane * 8 + c * 256;
        __half2 hh[4];
#pragma unroll
        for (int j = 0; j < 4; j++) {
            float w0 = nf_w[base + j * 2], w1 = nf_w[base + j * 2 + 1];
            hh[j] = __floats2half2_rn(vals[c * 8 + j * 2] * r * w0,
                                      vals[c * 8 + j * 2 + 1] * r * w1);
        }
        *(uint4*)(o + base) = *(uint4*)hh;
    }
}

// ---------------- attention: one warp per (n*t, head), 8 warps/CTA --------
__global__ __launch_bounds__(256) void k_attn() {
    __shared__ __align__(16) float s[8][17 * 64];   // per row: k[32] | v[32]
    int wrp  = threadIdx.x >> 5;
    int lane = threadIdx.x & 31;
    int bh = blockIdx.x * 8 + wrp;
    int b  = bh >> 2;
    int hh = bh & 3;

    const __half* src = g_qkv + (size_t)b * (17 * 384) + hh * 32;
    float* sm = s[wrp];

    // load K,V slices: 17 rows x 2 mats x 4 16B-chunks = 136 chunks
    for (int c = lane; c < 136; c += 32) {
        int row  = c >> 3;
        int m    = (c & 7) >> 2;           // 0 = K, 1 = V
        int part = c & 3;
        uint4 u = *(const uint4*)(src + (size_t)row * 384 + 128 + m * 128 + part * 8);
        float* dst = &sm[row * 64 + m * 32 + part * 8];
        __half2* h = (__half2*)&u;
#pragma unroll
        for (int j = 0; j < 4; j++) {
            float2 f = __half22float2(h[j]);
            dst[j * 2] = f.x; dst[j * 2 + 1] = f.y;
        }
    }
    __syncwarp();

    if (lane < 17) {
        int q = lane;
        float qv[32];
        const uint4* qp = (const uint4*)(src + (size_t)q * 384);
#pragma unroll
        for (int i = 0; i < 4; i++) {
            uint4 u = qp[i];
            __half2* h = (__half2*)&u;
#pragma unroll
            for (int j = 0; j < 4; j++) {
                float2 f = __half22float2(h[j]);
                qv[i * 8 + j * 2] = f.x; qv[i * 8 + j * 2 + 1] = f.y;
            }
        }
        float sc[17];
        float mx = -1e30f;
#pragma unroll
        for (int j = 0; j < 17; j++) {
            const float* kp = &sm[j * 64];
            float a = 0.f;
#pragma unroll
            for (int i = 0; i < 8; i++) {
                float4 v = *(const float4*)(kp + i * 4);
                a += qv[i * 4] * v.x + qv[i * 4 + 1] * v.y +
                     qv[i * 4 + 2] * v.z + qv[i * 4 + 3] * v.w;
            }
            a *= 0.17677669529663687f;   // 1/sqrt(32)
            sc[j] = a;
            mx = fmaxf(mx, a);
        }
        float sum = 0.f;
#pragma unroll
        for (int j = 0; j < 17; j++) { sc[j] = __expf(sc[j] - mx); sum += sc[j]; }
        float inv = 1.f / sum;
        float ov[32];
#pragma unroll
        for (int i = 0; i < 32; i++) ov[i] = 0.f;
#pragma unroll
        for (int j = 0; j < 17; j++) {
            float p = sc[j] * inv;
            const float* vp = &sm[j * 64 + 32];
#pragma unroll
            for (int i = 0; i < 8; i++) {
                float4 v = *(const float4*)(vp + i * 4);
                ov[i * 4]     += p * v.x;
                ov[i * 4 + 1] += p * v.y;
                ov[i * 4 + 2] += p * v.z;
                ov[i * 4 + 3] += p * v.w;
            }
        }
        __half* op = g_o + ((size_t)b * 17 + q) * 128 + hh * 32;
        union { __half2 h2[16]; uint4 u4[4]; } ob;
#pragma unroll
        for (int i = 0; i < 16; i++)
            ob.h2[i] = __floats2half2_rn(ov[2 * i], ov[2 * i + 1]);
        uint4* o4 = (uint4*)op;
#pragma unroll
        for (int i = 0; i < 4; i++) o4[i] = ob.u4[i];
    }
}

// ---------------- launch --------------------------------------------------
extern "C" void kernel_launch(void* const* d_in, const int* in_sizes, int n_in,
                              void* d_out, int out_size)
{
    const float* x     = (const float*)d_in[0];
    const float* tm_w1 = (const float*)d_in[1];
    const float* tm_b1 = (const float*)d_in[2];
    const float* tm_w2 = (const float*)d_in[3];
    const float* tm_b2 = (const float*)d_in[4];
    const float* na_w  = (const float*)d_in[5];
    const float* in_w  = (const float*)d_in[6];
    const float* in_b  = (const float*)d_in[7];
    const float* out_w = (const float*)d_in[8];
    const float* out_b = (const float*)d_in[9];
    const float* nf_w  = (const float*)d_in[10];
    const float* cm_w1 = (const float*)d_in[11];
    const float* cm_b1 = (const float*)d_in[12];
    const float* cm_w2 = (const float*)d_in[13];
    const float* cm_b2 = (const float*)d_in[14];
    float* out = (float*)d_out;

    const int mt = (MROWS + 127) / 128;  // 1033 M-tiles

    k_front<<<NT_B + 1024, 512>>>(x, tm_w1, tm_b1, tm_w2, tm_b2, na_w,
                                  in_w, out_w, cm_w1, cm_w2);
    k_gemm_qkv<<<dim3(3, mt), 256>>>(in_b);
    k_attn<<<NT_B / 2, 256>>>();
    k_gemm_proj<<<dim3(1, mt), 256>>>(out_b);
    k_prep_f<<<(MROWS + 7) / 8, 256>>>(nf_w);
    k_gemm_mlp1<<<dim3(8, mt), 256>>>(cm_b1);
    k_gemm_mlp2<<<dim3(4, mt), 256>>>(cm_b2, x, out);
}

// round 14
// speedup vs baseline: 1.0831x; 1.0168x over previous
#include <cuda_runtime.h>
#include <cuda_fp16.h>
#include <cstdint>
#include <math.h>

// Problem dims
#define N_B   32
#define T_B   243
#define V_B   17
#define NT_B  (N_B * T_B)          // 7776
#define MROWS (NT_B * V_B)         // 132192
#define MT256 ((MROWS + 255) / 256)

// ---------------- scratch (static device memory; no allocations) ----------
__device__ __half g_xc [67682304];   // M*512  concat (xm_out | xa_out)
__device__ __half g_qkv[50761728];   // M*384
__device__ __half g_o  [16920576];   // M*128
__device__ __half g_h  [135364608];  // M*1024
__device__ __half h_xa [16920576];   // M*128  normalized attn input
__device__ __half h_xn [67682304];   // M*512  normalized MLP input
__device__ __half h_in_w [49152];
__device__ __half h_out_w[16384];
__device__ __half h_cm_w1[524288];
__device__ __half h_cm_w2[524288];

// ---------------- helpers -------------------------------------------------
__device__ __forceinline__ float gelu_f(float v) {
    return 0.5f * v * (1.0f + erff(v * 0.7071067811865475f));
}
__device__ __forceinline__ uint32_t smaddr(const void* p) {
    return (uint32_t)__cvta_generic_to_shared(p);
}
__device__ __forceinline__ void ldsm4(uint32_t* r, uint32_t a) {
    asm volatile("ldmatrix.sync.aligned.m8n8.x4.shared.b16 {%0,%1,%2,%3}, [%4];"
        : "=r"(r[0]), "=r"(r[1]), "=r"(r[2]), "=r"(r[3]) : "r"(a));
}
// fp16-ACCUMULATE mma: D(f16x2 x2) = A*B + D
__device__ __forceinline__ void hmma16(uint32_t* d, const uint32_t* a, const uint32_t* b) {
    asm volatile(
        "mma.sync.aligned.m16n8k16.row.col.f16.f16.f16.f16 "
        "{%0,%1},{%2,%3,%4,%5},{%6,%7},{%0,%1};"
        : "+r"(d[0]), "+r"(d[1])
        : "r"(a[0]), "r"(a[1]), "r"(a[2]), "r"(a[3]), "r"(b[0]), "r"(b[1]));
}
__device__ __forceinline__ void cp16(uint32_t dst, const void* src, bool pred) {
    int sz = pred ? 16 : 0;
    asm volatile("cp.async.cg.shared.global [%0], [%1], 16, %2;\n"
        :: "r"(dst), "l"(src), "r"(sz));
}
__device__ __forceinline__ void cp_commit() {
    asm volatile("cp.async.commit_group;\n" ::: "memory");
}
template <int NN>
__device__ __forceinline__ void cp_wait() {
    asm volatile("cp.async.wait_group %0;\n" :: "n"(NN) : "memory");
}

// swizzled offset inside a (rows x 32) fp16 stage tile (conflict-free for
// cp.async 16B stores and ldmatrix 8x16B reads)
__device__ __forceinline__ int sw_off(int row, int col) {
    return row * 32 + ((((col >> 3) ^ (row >> 1)) & 3) << 3) + (col & 7);
}

// ---------------- fp16 GEMM: out = act(A * W^T + bias) --------------------
// CTA tile 256(M) x 128(N), 8 warps of 64x64 (hmma:ldsm ratio 4.0, 4 warps
// per SMSP at 2 CTAs/SM), K-tile 32, 3-stage cp.async, fp16 accumulators.
// Stage: A 256x32h (16KB) + B 128x32h (8KB) = 24KB; 3 stages = 72KB dynamic.
// MODE: 0 = bias, 1 = bias+gelu, 2 = bias+residual(fp32 x, stride 512)
#define STAGES 3
#define STAGE_BYTES 24576
#define GEMM_SMEM (STAGES * STAGE_BYTES)

template <int MODE, typename OT>
__device__ __forceinline__ void gemm_core(
    const __half* __restrict__ A, int lda,
    const __half* __restrict__ W, int K,
    const float* __restrict__ bias,
    const float* __restrict__ residual,
    OT* __restrict__ out, int ldc, int coff,
    int M)
{
    extern __shared__ char dynsmem[];
    const uint32_t sb = smaddr(dynsmem);

    const int tid  = threadIdx.x;
    const int lane = tid & 31;
    const int warp = tid >> 5;
    const int wm   = (warp & 3) * 64;    // 4 warps along M
    const int wn   = (warp >> 2) * 64;   // 2 warps along N
    const int n0   = blockIdx.x * 128;   // N fastest -> A-tile L2 reuse
    const int m0   = blockIdx.y * 256;

    uint32_t stA[STAGES], stB[STAGES];
#pragma unroll
    for (int s = 0; s < STAGES; s++) {
        stA[s] = sb + s * STAGE_BYTES;           // 256x32 halfs
        stB[s] = stA[s] + 16384;                 // 128x32 halfs
    }

    uint32_t acc[4][8][2] = {};          // fp16x2 accumulators (64 regs)

    // staging: A 1024 chunks (4/thread) + B 512 chunks (2/thread)
    auto issue = [&](int s, int kk) {
#pragma unroll
        for (int i = 0; i < 4; i++) {
            int ch = tid + i * 256;              // 0..1023
            int r  = ch >> 2, g = ch & 3;
            cp16(stA[s] + sw_off(r, g * 8) * 2,
                 A + (size_t)(m0 + r) * lda + kk + g * 8, (m0 + r) < M);
        }
#pragma unroll
        for (int i = 0; i < 2; i++) {
            int ch = tid + i * 256;              // 0..511
            int r  = ch >> 2, g = ch & 3;
            cp16(stB[s] + sw_off(r, g * 8) * 2,
                 W + (size_t)(n0 + r) * K + kk + g * 8, true);
        }
    };

    auto compute = [&](int s) {
#pragma unroll
        for (int ks = 0; ks < 2; ks++) {
            const int c = ks * 16 + 8 * (lane >> 4);
            uint32_t a[4][4], b[4][4];
#pragma unroll
            for (int mt = 0; mt < 4; mt++) {
                int r = wm + mt * 16 + (lane & 15);
                ldsm4(a[mt], stA[s] + sw_off(r, c) * 2);
            }
#pragma unroll
            for (int np = 0; np < 4; np++) {
                int r = wn + np * 16 + (lane & 15);
                ldsm4(b[np], stB[s] + sw_off(r, c) * 2);
            }
#pragma unroll
            for (int mt = 0; mt < 4; mt++)
#pragma unroll
                for (int nt = 0; nt < 8; nt++) {
                    uint32_t bb[2] = { b[nt >> 1][nt & 1], b[nt >> 1][(nt & 1) + 2] };
                    hmma16(acc[mt][nt], a[mt], bb);
                }
        }
    };

    const int nk = K >> 5;
    int fetch = 0;
#pragma unroll
    for (int s = 0; s < STAGES - 1; s++) {
        if (fetch < nk) issue(fetch % STAGES, fetch << 5);
        cp_commit();
        fetch++;
    }
    for (int kt = 0; kt < nk; kt++) {
        cp_wait<STAGES - 2>();
        __syncthreads();
        compute(kt % STAGES);
        __syncthreads();
        if (fetch < nk) issue(fetch % STAGES, fetch << 5);
        cp_commit();
        fetch++;
    }

    // epilogue: unpack fp16 accumulators
    const int er = lane >> 2;
    const int ec = (lane & 3) * 2;
#pragma unroll
    for (int mt = 0; mt < 4; mt++) {
#pragma unroll
        for (int hh = 0; hh < 2; hh++) {
            int row = m0 + wm + mt * 16 + er + hh * 8;
            if (row >= M) continue;
#pragma unroll
            for (int nt = 0; nt < 8; nt++) {
                int col  = wn + nt * 8 + ec;
                int gcol = n0 + col;
                float2 f = __half22float2(((__half2*)acc[mt][nt])[hh]);
                float v0 = f.x + bias[gcol];
                float v1 = f.y + bias[gcol + 1];
                if (MODE == 1) { v0 = gelu_f(v0); v1 = gelu_f(v1); }
                if (MODE == 2) {
                    const float* rp = residual + (size_t)row * 512 + coff + gcol;
                    v0 += rp[0]; v1 += rp[1];
                }
                if constexpr (sizeof(OT) == 2) {
                    *(__half2*)(out + (size_t)row * ldc + coff + gcol) =
                        __floats2half2_rn(v0, v1);
                } else {
                    *(float2*)(out + (size_t)row * ldc + coff + gcol) =
                        make_float2(v0, v1);
                }
            }
        }
    }
}

// ---------------- GEMM wrappers ------------------------------------------
__global__ __launch_bounds__(256, 2) void k_gemm_qkv(const float* __restrict__ in_b) {
    gemm_core<0, __half>(h_xa, 128, h_in_w, 128, in_b, nullptr,
                         g_qkv, 384, 0, MROWS);
}
__global__ __launch_bounds__(256, 2) void k_gemm_proj(const float* __restrict__ out_b) {
    gemm_core<0, __half>(g_o, 128, h_out_w, 128, out_b, nullptr,
                         g_xc, 512, 384, MROWS);
}
__global__ __launch_bounds__(256, 2) void k_gemm_mlp1(const float* __restrict__ cm_b1) {
    gemm_core<1, __half>(h_xn, 512, h_cm_w1, 512, cm_b1, nullptr,
                         g_h, 1024, 0, MROWS);
}
__global__ __launch_bounds__(256, 2) void k_gemm_mlp2(
    const float* __restrict__ cm_b2, const float* __restrict__ x,
    float* __restrict__ out)
{
    gemm_core<2, float>(g_h, 1024, h_cm_w2, 1024, cm_b2, x,
                        out, 512, 0, MROWS);
}

// ---------------- fused: token mixer + prep_a + weight convert ------------
// Blocks [0, NT_B): 512 threads — t<384 do the V-mixer for channel t,
//   t>=384 (4 warps) do RMSNorm-A prep for the block's 17 rows.
// Blocks [NT_B, NT_B+1024): fp32->fp16 weight conversion.
__global__ __launch_bounds__(512) void k_front(
    const float* __restrict__ x,
    const float* __restrict__ w1, const float* __restrict__ b1,
    const float* __restrict__ w2, const float* __restrict__ b2,
    const float* __restrict__ na_w,
    const float* __restrict__ in_w, const float* __restrict__ out_w,
    const float* __restrict__ cm_w1, const float* __restrict__ cm_w2)
{
    int tid = threadIdx.x;
    if (blockIdx.x >= NT_B) {
        int i = (blockIdx.x - NT_B) * 512 + tid;
        if (i < 49152)  h_in_w[i]  = __float2half(in_w[i]);
        if (i < 16384)  h_out_w[i] = __float2half(out_w[i]);
        if (i < 524288) {
            h_cm_w1[i] = __float2half(cm_w1[i]);
            h_cm_w2[i] = __float2half(cm_w2[i]);
        }
        return;
    }

    __shared__ float sw1[289], sw2[289], sb1[17], sb2[17];
    if (tid < 289) { sw1[tid] = w1[tid]; sw2[tid] = w2[tid]; }
    if (tid < 17)  { sb1[tid] = b1[tid]; sb2[tid] = b2[tid]; }
    __syncthreads();

    size_t base = (size_t)blockIdx.x * V_B * 512;

    if (tid < 384) {
        int d = tid;  // channel 0..383
        float xv[17];
#pragma unroll
        for (int v = 0; v < 17; v++) xv[v] = x[base + (size_t)v * 512 + d];
        float h[17];
#pragma unroll
        for (int u = 0; u < 17; u++) {
            float s = sb1[u];
#pragma unroll
            for (int v = 0; v < 17; v++) s += sw1[u * 17 + v] * xv[v];
            h[u] = gelu_f(s);
        }
#pragma unroll
        for (int u = 0; u < 17; u++) {
            float s = sb2[u];
#pragma unroll
            for (int v = 0; v < 17; v++) s += sw2[u * 17 + v] * h[v];
            g_xc[base + (size_t)u * 512 + d] = __float2half(s);
        }
    } else {
        // prep_a for the 17 rows of this (n,t): 4 warps, rows wrp, wrp+4, ...
        int wrp  = (tid - 384) >> 5;
        int lane = tid & 31;
        size_t row0 = (size_t)blockIdx.x * V_B;
        float4 w = *(const float4*)(na_w + lane * 4);
        for (int r = wrp; r < 17; r += 4) {
            size_t row = row0 + r;
            const float* p = x + row * 512 + 384;
            float4 v = *(const float4*)(p + lane * 4);
            float ss = v.x * v.x + v.y * v.y + v.z * v.z + v.w * v.w;
#pragma unroll
            for (int s = 16; s; s >>= 1) ss += __shfl_xor_sync(0xffffffffu, ss, s);
            float rr = rsqrtf(ss * (1.0f / 128.0f) + 1e-6f);
            __half2* o = (__half2*)(h_xa + row * 128 + lane * 4);
            o[0] = __floats2half2_rn(v.x * rr * w.x, v.y * rr * w.y);
            o[1] = __floats2half2_rn(v.z * rr * w.z, v.w * rr * w.w);
        }
    }
}

// ---------------- RMSNorm prep (full row) ---------------------------------
__global__ __launch_bounds__(256) void k_prep_f(const float* __restrict__ nf_w) {
    int row = blockIdx.x * 8 + (threadIdx.x >> 5);
    if (row >= MROWS) return;
    int lane = threadIdx.x & 31;
    const __half* p = g_xc + (size_t)row * 512;
    float vals[16];
    float ss = 0.f;
#pragma unroll
    for (int c = 0; c < 2; c++) {
        uint4 u = *(const uint4*)(p + lane * 8 + c * 256);
        __half2* h = (__half2*)&u;
#pragma unroll
        for (int j = 0; j < 4; j++) {
            float2 f = __half22float2(h[j]);
            vals[c * 8 + j * 2] = f.x; vals[c * 8 + j * 2 + 1] = f.y;
            ss += f.x * f.x + f.y * f.y;
        }
    }
#pragma unroll
    for (int s = 16; s; s >>= 1) ss += __shfl_xor_sync(0xffffffffu, ss, s);
    float r = rsqrtf(ss * (1.0f / 512.0f) + 1e-6f);
    __half* o = h_xn + (size_t)row * 512;
#pragma unroll
    for (int c = 0; c < 2; c++) {
        int base = lane * 8 + c * 256;
        __half2 hh[4];
#pragma unroll
        for (int j = 0; j < 4; j++) {
            float w0 = nf_w[base + j * 2], w1 = nf_w[base + j * 2 + 1];
            hh[j] = __floats2half2_rn(vals[c * 8 + j * 2] * r * w0,
                                      vals[c * 8 + j * 2 + 1] * r * w1);
        }
        *(uint4*)(o + base) = *(uint4*)hh;
    }
}

// ---------------- attention: one warp per (n*t, head), 8 warps/CTA --------
__global__ __launch_bounds__(256) void k_attn() {
    __shared__ __align__(16) float s[8][17 * 64];   // per row: k[32] | v[32]
    int wrp  = threadIdx.x >> 5;
    int lane = threadIdx.x & 31;
    int bh = blockIdx.x * 8 + wrp;
    int b  = bh >> 2;
    int hh = bh & 3;

    const __half* src = g_qkv + (size_t)b * (17 * 384) + hh * 32;
    float* sm = s[wrp];

    // load K,V slices: 17 rows x 2 mats x 4 16B-chunks = 136 chunks
    for (int c = lane; c < 136; c += 32) {
        int row  = c >> 3;
        int m    = (c & 7) >> 2;           // 0 = K, 1 = V
        int part = c & 3;
        uint4 u = *(const uint4*)(src + (size_t)row * 384 + 128 + m * 128 + part * 8);
        float* dst = &sm[row * 64 + m * 32 + part * 8];
        __half2* h = (__half2*)&u;
#pragma unroll
        for (int j = 0; j < 4; j++) {
            float2 f = __half22float2(h[j]);
            dst[j * 2] = f.x; dst[j * 2 + 1] = f.y;
        }
    }
    __syncwarp();

    if (lane < 17) {
        int q = lane;
        float qv[32];
        const uint4* qp = (const uint4*)(src + (size_t)q * 384);
#pragma unroll
        for (int i = 0; i < 4; i++) {
            uint4 u = qp[i];
            __half2* h = (__half2*)&u;
#pragma unroll
            for (int j = 0; j < 4; j++) {
                float2 f = __half22float2(h[j]);
                qv[i * 8 + j * 2] = f.x; qv[i * 8 + j * 2 + 1] = f.y;
            }
        }
        float sc[17];
        float mx = -1e30f;
#pragma unroll
        for (int j = 0; j < 17; j++) {
            const float* kp = &sm[j * 64];
            float a = 0.f;
#pragma unroll
            for (int i = 0; i < 8; i++) {
                float4 v = *(const float4*)(kp + i * 4);
                a += qv[i * 4] * v.x + qv[i * 4 + 1] * v.y +
                     qv[i * 4 + 2] * v.z + qv[i * 4 + 3] * v.w;
            }
            a *= 0.17677669529663687f;   // 1/sqrt(32)
            sc[j] = a;
            mx = fmaxf(mx, a);
        }
        float sum = 0.f;
#pragma unroll
        for (int j = 0; j < 17; j++) { sc[j] = __expf(sc[j] - mx); sum += sc[j]; }
        float inv = 1.f / sum;
        float ov[32];
#pragma unroll
        for (int i = 0; i < 32; i++) ov[i] = 0.f;
#pragma unroll
        for (int j = 0; j < 17; j++) {
            float p = sc[j] * inv;
            const float* vp = &sm[j * 64 + 32];
#pragma unroll
            for (int i = 0; i < 8; i++) {
                float4 v = *(const float4*)(vp + i * 4);
                ov[i * 4]     += p * v.x;
                ov[i * 4 + 1] += p * v.y;
                ov[i * 4 + 2] += p * v.z;
                ov[i * 4 + 3] += p * v.w;
            }
        }
        __half* op = g_o + ((size_t)b * 17 + q) * 128 + hh * 32;
        union { __half2 h2[16]; uint4 u4[4]; } ob;
#pragma unroll
        for (int i = 0; i < 16; i++)
            ob.h2[i] = __floats2half2_rn(ov[2 * i], ov[2 * i + 1]);
        uint4* o4 = (uint4*)op;
#pragma unroll
        for (int i = 0; i < 4; i++) o4[i] = ob.u4[i];
    }
}

// ---------------- launch --------------------------------------------------
extern "C" void kernel_launch(void* const* d_in, const int* in_sizes, int n_in,
                              void* d_out, int out_size)
{
    const float* x     = (const float*)d_in[0];
    const float* tm_w1 = (const float*)d_in[1];
    const float* tm_b1 = (const float*)d_in[2];
    const float* tm_w2 = (const float*)d_in[3];
    const float* tm_b2 = (const float*)d_in[4];
    const float* na_w  = (const float*)d_in[5];
    const float* in_w  = (const float*)d_in[6];
    const float* in_b  = (const float*)d_in[7];
    const float* out_w = (const float*)d_in[8];
    const float* out_b = (const float*)d_in[9];
    const float* nf_w  = (const float*)d_in[10];
    const float* cm_w1 = (const float*)d_in[11];
    const float* cm_b1 = (const float*)d_in[12];
    const float* cm_w2 = (const float*)d_in[13];
    const float* cm_b2 = (const float*)d_in[14];
    float* out = (float*)d_out;

    static int attr_done = 0;
    if (!attr_done) {
        cudaFuncSetAttribute(k_gemm_qkv,  cudaFuncAttributeMaxDynamicSharedMemorySize, GEMM_SMEM);
        cudaFuncSetAttribute(k_gemm_proj, cudaFuncAttributeMaxDynamicSharedMemorySize, GEMM_SMEM);
        cudaFuncSetAttribute(k_gemm_mlp1, cudaFuncAttributeMaxDynamicSharedMemorySize, GEMM_SMEM);
        cudaFuncSetAttribute(k_gemm_mlp2, cudaFuncAttributeMaxDynamicSharedMemorySize, GEMM_SMEM);
        attr_done = 1;
    }

    k_front<<<NT_B + 1024, 512>>>(x, tm_w1, tm_b1, tm_w2, tm_b2, na_w,
                                  in_w, out_w, cm_w1, cm_w2);
    k_gemm_qkv<<<dim3(3, MT256), 256, GEMM_SMEM>>>(in_b);
    k_attn<<<NT_B / 2, 256>>>();
    k_gemm_proj<<<dim3(1, MT256), 256, GEMM_SMEM>>>(out_b);
    k_prep_f<<<(MROWS + 7) / 8, 256>>>(nf_w);
    k_gemm_mlp1<<<dim3(8, MT256), 256, GEMM_SMEM>>>(cm_b1);
    k_gemm_mlp2<<<dim3(4, MT256), 256, GEMM_SMEM>>>(cm_b2, x, out);
}